// round 1
// baseline (speedup 1.0000x reference)
#include <cuda_runtime.h>
#include <math.h>

#define VV 10000
#define EE 512
#define HH 1024
#define SS 64
#define BB 64

#define SBH (SS*BB*HH)
#define BH  (BB*HH)

// ---------------- device scratch (no cudaMalloc allowed) ----------------
__device__ float g_X0[3u * SBH];        // precomputed x-side of layer0 gates (+bias)
__device__ float g_H1all[SBH];          // all layer-1 hidden states (for batched Wout GEMM)
__device__ float g_h0[BH];              // layer0 hidden state
__device__ float g_rh0[BH];             // r0 * h0
__device__ float g_z0[BH];
__device__ float g_z1[BH];
__device__ float g_cat1[BB * 2 * HH];   // [x1, h1]
__device__ float g_cat1h[BB * 2 * HH];  // [x1, r1*h1]

__device__ __forceinline__ float sigm(float x) { return 1.0f / (1.0f + expf(-x)); }

// ---------------- init: load init_hidden into state buffers ----------------
__global__ void k_init(const float* __restrict__ h_init) {
    int i = blockIdx.x * blockDim.x + threadIdx.x;
    if (i < BH) {
        g_h0[i] = h_init[i];
        int b = i >> 10, n = i & (HH - 1);
        g_cat1[b * 2 * HH + HH + n] = h_init[BH + i];
    }
}

// ---------------- big-tile GEMM (64x64x16, 256 thr, 4x4/thread) ----------------
// k_embed: X0[g][t*B+b][n] = sum_k emb[ids[t,b]][k] * Wg[k][n] + biasg[n]   (K=E=512)
__global__ __launch_bounds__(256) void k_embed(
    const int* __restrict__ ids, const float* __restrict__ emb,
    const float* __restrict__ Wr, const float* __restrict__ Wz, const float* __restrict__ Wh,
    const float* __restrict__ br, const float* __restrict__ bz, const float* __restrict__ bh)
{
    const int g = blockIdx.z;
    const float* __restrict__ W    = (g == 0) ? Wr : ((g == 1) ? Wz : Wh);
    const float* __restrict__ bias = (g == 0) ? br : ((g == 1) ? bz : bh);
    float* __restrict__ out = g_X0 + (size_t)g * SBH;

    __shared__ __align__(16) float As[16][68];
    __shared__ __align__(16) float Ws[16][64];
    const int tid = threadIdx.x;
    const int bm = blockIdx.y * 64, bn = blockIdx.x * 64;
    const int lr = tid >> 2, lk = (tid & 3) * 4;
    const int wk = tid >> 4, wn = (tid & 15) * 4;
    const int tx = tid & 15, ty = tid >> 4;
    const float* __restrict__ arow = emb + (size_t)ids[bm + lr] * EE + lk;

    float acc[4][4];
#pragma unroll
    for (int i = 0; i < 4; i++)
#pragma unroll
        for (int j = 0; j < 4; j++) acc[i][j] = 0.f;

    for (int k0 = 0; k0 < EE; k0 += 16) {
        float4 av = *(const float4*)(arow + k0);
        As[lk + 0][lr] = av.x; As[lk + 1][lr] = av.y;
        As[lk + 2][lr] = av.z; As[lk + 3][lr] = av.w;
        *(float4*)&Ws[wk][wn] = *(const float4*)(W + (size_t)(k0 + wk) * HH + bn + wn);
        __syncthreads();
#pragma unroll
        for (int kk = 0; kk < 16; kk++) {
            float4 a = *(const float4*)&As[kk][ty * 4];
            float4 w = *(const float4*)&Ws[kk][tx * 4];
            acc[0][0] += a.x * w.x; acc[0][1] += a.x * w.y; acc[0][2] += a.x * w.z; acc[0][3] += a.x * w.w;
            acc[1][0] += a.y * w.x; acc[1][1] += a.y * w.y; acc[1][2] += a.y * w.z; acc[1][3] += a.y * w.w;
            acc[2][0] += a.z * w.x; acc[2][1] += a.z * w.y; acc[2][2] += a.z * w.z; acc[2][3] += a.z * w.w;
            acc[3][0] += a.w * w.x; acc[3][1] += a.w * w.y; acc[3][2] += a.w * w.z; acc[3][3] += a.w * w.w;
        }
        __syncthreads();
    }
    float4 bv = *(const float4*)(bias + bn + tx * 4);
#pragma unroll
    for (int i = 0; i < 4; i++) {
        int row = bm + ty * 4 + i;
        float* o = out + (size_t)row * HH + bn + tx * 4;
        o[0] = acc[i][0] + bv.x; o[1] = acc[i][1] + bv.y;
        o[2] = acc[i][2] + bv.z; o[3] = acc[i][3] + bv.w;
    }
}

// k_out: logits[m][v] = sum_k H1all[m][k] * Wout[k][v] + bout[v]   (M=4096, N=10000, K=1024)
__global__ __launch_bounds__(256) void k_out(
    const float* __restrict__ Wout, const float* __restrict__ bout,
    float* __restrict__ logits)
{
    __shared__ __align__(16) float As[16][68];
    __shared__ __align__(16) float Ws[16][64];
    const int tid = threadIdx.x;
    const int bm = blockIdx.y * 64, bn = blockIdx.x * 64;
    const int lr = tid >> 2, lk = (tid & 3) * 4;
    const int wk = tid >> 4, wn = (tid & 15) * 4;
    const int tx = tid & 15, ty = tid >> 4;
    const float* __restrict__ arow = g_H1all + (size_t)(bm + lr) * HH + lk;
    const bool wok = (bn + wn + 3) < VV;

    float acc[4][4];
#pragma unroll
    for (int i = 0; i < 4; i++)
#pragma unroll
        for (int j = 0; j < 4; j++) acc[i][j] = 0.f;

    for (int k0 = 0; k0 < HH; k0 += 16) {
        float4 av = *(const float4*)(arow + k0);
        As[lk + 0][lr] = av.x; As[lk + 1][lr] = av.y;
        As[lk + 2][lr] = av.z; As[lk + 3][lr] = av.w;
        float4 wv;
        const float* wp = Wout + (size_t)(k0 + wk) * VV;
        if (wok) {
            wv = *(const float4*)(wp + bn + wn);
        } else {
            wv.x = (bn + wn + 0 < VV) ? wp[bn + wn + 0] : 0.f;
            wv.y = (bn + wn + 1 < VV) ? wp[bn + wn + 1] : 0.f;
            wv.z = (bn + wn + 2 < VV) ? wp[bn + wn + 2] : 0.f;
            wv.w = (bn + wn + 3 < VV) ? wp[bn + wn + 3] : 0.f;
        }
        *(float4*)&Ws[wk][wn] = wv;
        __syncthreads();
#pragma unroll
        for (int kk = 0; kk < 16; kk++) {
            float4 a = *(const float4*)&As[kk][ty * 4];
            float4 w = *(const float4*)&Ws[kk][tx * 4];
            acc[0][0] += a.x * w.x; acc[0][1] += a.x * w.y; acc[0][2] += a.x * w.z; acc[0][3] += a.x * w.w;
            acc[1][0] += a.y * w.x; acc[1][1] += a.y * w.y; acc[1][2] += a.y * w.z; acc[1][3] += a.y * w.w;
            acc[2][0] += a.z * w.x; acc[2][1] += a.z * w.y; acc[2][2] += a.z * w.z; acc[2][3] += a.z * w.w;
            acc[3][0] += a.w * w.x; acc[3][1] += a.w * w.y; acc[3][2] += a.w * w.z; acc[3][3] += a.w * w.w;
        }
        __syncthreads();
    }
#pragma unroll
    for (int i = 0; i < 4; i++) {
        int row = bm + ty * 4 + i;
#pragma unroll
        for (int j = 0; j < 4; j++) {
            int col = bn + tx * 4 + j;
            if (col < VV) logits[(size_t)row * VV + col] = acc[i][j] + bout[col];
        }
    }
}

// ---------------- per-step small GEMM core (BM=64, BN=8, BK=32, 128 thr) ----------------
// acc[i] = sum_k A[rowg*4+i][k] * W[k][bn+col]  with W row-major, ldw = HH
__device__ __forceinline__ void step_gemm(
    const float* __restrict__ A, int lda, int K,
    const float* __restrict__ W, int bn, float acc[4])
{
    __shared__ __align__(16) float As[32][68];
    __shared__ __align__(16) float Ws[32][8];
    const int tid = threadIdx.x;
    const int col  = tid & 7;
    const int rowg = tid >> 3;          // 0..15
    const int ar = tid >> 1;            // 0..63  (A-load row)
    const int ak = (tid & 1) * 16;      // 0 or 16 (A-load k base)
    const int wk = tid >> 2;            // 0..31
    const int wn = (tid & 3) * 2;

    acc[0] = acc[1] = acc[2] = acc[3] = 0.f;
    const float* __restrict__ Arow = A + (size_t)ar * lda + ak;

    for (int k0 = 0; k0 < K; k0 += 32) {
#pragma unroll
        for (int j = 0; j < 4; ++j) {
            float4 v = *(const float4*)(Arow + k0 + j * 4);
            As[ak + j * 4 + 0][ar] = v.x;
            As[ak + j * 4 + 1][ar] = v.y;
            As[ak + j * 4 + 2][ar] = v.z;
            As[ak + j * 4 + 3][ar] = v.w;
        }
        float2 wv = *(const float2*)(W + (size_t)(k0 + wk) * HH + bn + wn);
        Ws[wk][wn] = wv.x; Ws[wk][wn + 1] = wv.y;
        __syncthreads();
#pragma unroll
        for (int kk = 0; kk < 32; ++kk) {
            float4 a = *(const float4*)&As[kk][rowg * 4];
            float  w = Ws[kk][col];
            acc[0] += a.x * w; acc[1] += a.y * w;
            acc[2] += a.z * w; acc[3] += a.w * w;
        }
        __syncthreads();
    }
}

// r0/z0: sigma(X0[g][t] + h0 @ W{r,z}0[E:,:]);  r-branch stores r*h0
__global__ __launch_bounds__(128) void k_gates0(int t,
    const float* __restrict__ Wr0, const float* __restrict__ Wz0)
{
    const int bn = blockIdx.x * 8;
    const int gate = blockIdx.y;
    const float* W = (gate ? Wz0 : Wr0) + (size_t)EE * HH;
    float acc[4];
    step_gemm(g_h0, HH, HH, W, bn, acc);
    const float* X = g_X0 + (size_t)gate * SBH + (size_t)t * BH;
    const int col = threadIdx.x & 7, rowg = threadIdx.x >> 3;
#pragma unroll
    for (int i = 0; i < 4; i++) {
        int idx = (rowg * 4 + i) * HH + bn + col;
        float v = sigm(acc[i] + X[idx]);
        if (gate == 0) g_rh0[idx] = v * g_h0[idx];
        else           g_z0[idx] = v;
    }
}

// hh0 = sigma(X0[2][t] + (r*h0) @ Wh0[E:,:]);  h0 <- (1-z)*h0 + z*hh0
__global__ __launch_bounds__(128) void k_cand0(int t, const float* __restrict__ Wh0)
{
    const int bn = blockIdx.x * 8;
    float acc[4];
    step_gemm(g_rh0, HH, HH, Wh0 + (size_t)EE * HH, bn, acc);
    const float* X = g_X0 + 2ull * SBH + (size_t)t * BH;
    const int col = threadIdx.x & 7, rowg = threadIdx.x >> 3;
#pragma unroll
    for (int i = 0; i < 4; i++) {
        int idx = (rowg * 4 + i) * HH + bn + col;
        float hh = sigm(acc[i] + X[idx]);
        float h = g_h0[idx], z = g_z0[idx];
        g_h0[idx] = (1.f - z) * h + z * hh;
    }
}

// x1 = sigma(h0 @ Wfc + bfc) -> cat1[:, :H], cat1h[:, :H]
__global__ __launch_bounds__(128) void k_fc(
    const float* __restrict__ Wfc, const float* __restrict__ bfc)
{
    const int bn = blockIdx.x * 8;
    float acc[4];
    step_gemm(g_h0, HH, HH, Wfc, bn, acc);
    const int col = threadIdx.x & 7, rowg = threadIdx.x >> 3;
#pragma unroll
    for (int i = 0; i < 4; i++) {
        int b = rowg * 4 + i, n = bn + col;
        float x1 = sigm(acc[i] + bfc[n]);
        g_cat1[b * 2 * HH + n] = x1;
        g_cat1h[b * 2 * HH + n] = x1;
    }
}

// r1/z1 = sigma([x1,h1] @ W{r,z}1 + b);  r-branch stores r1*h1 into cat1h[:, H:]
__global__ __launch_bounds__(128) void k_gates1(
    const float* __restrict__ Wr1, const float* __restrict__ Wz1,
    const float* __restrict__ br1, const float* __restrict__ bz1)
{
    const int bn = blockIdx.x * 8;
    const int gate = blockIdx.y;
    const float* W = gate ? Wz1 : Wr1;
    const float* bias = gate ? bz1 : br1;
    float acc[4];
    step_gemm(g_cat1, 2 * HH, 2 * HH, W, bn, acc);
    const int col = threadIdx.x & 7, rowg = threadIdx.x >> 3;
#pragma unroll
    for (int i = 0; i < 4; i++) {
        int b = rowg * 4 + i, n = bn + col;
        float v = sigm(acc[i] + bias[n]);
        if (gate == 0) {
            float h1 = g_cat1[b * 2 * HH + HH + n];
            g_cat1h[b * 2 * HH + HH + n] = v * h1;
        } else {
            g_z1[b * HH + n] = v;
        }
    }
}

// hh1 = sigma([x1, r1*h1] @ Wh1 + bh1); h1 <- (1-z1)*h1 + z1*hh1; store into H1all[t]
__global__ __launch_bounds__(128) void k_cand1(int t,
    const float* __restrict__ Wh1, const float* __restrict__ bh1)
{
    const int bn = blockIdx.x * 8;
    float acc[4];
    step_gemm(g_cat1h, 2 * HH, 2 * HH, Wh1, bn, acc);
    const int col = threadIdx.x & 7, rowg = threadIdx.x >> 3;
#pragma unroll
    for (int i = 0; i < 4; i++) {
        int b = rowg * 4 + i, n = bn + col;
        float hh = sigm(acc[i] + bh1[n]);
        float h1 = g_cat1[b * 2 * HH + HH + n];
        float z  = g_z1[b * HH + n];
        float hn = (1.f - z) * h1 + z * hh;
        g_cat1[b * 2 * HH + HH + n] = hn;
        g_H1all[(size_t)t * BH + b * HH + n] = hn;
    }
}

// h_final = [h0, h1]  appended after logits
__global__ void k_hfinal(float* __restrict__ out) {
    int i = blockIdx.x * blockDim.x + threadIdx.x;
    if (i < BH) {
        out[i] = g_h0[i];
        int b = i >> 10, n = i & (HH - 1);
        out[BH + i] = g_cat1[b * 2 * HH + HH + n];
    }
}

extern "C" void kernel_launch(void* const* d_in, const int* in_sizes, int n_in,
                              void* d_out, int out_size)
{
    const int*   ids    = (const int*)d_in[0];
    const float* h_init = (const float*)d_in[1];
    const float* emb    = (const float*)d_in[2];
    const float* Wr0 = (const float*)d_in[3],  *Wz0 = (const float*)d_in[4],  *Wh0 = (const float*)d_in[5];
    const float* br0 = (const float*)d_in[6],  *bz0 = (const float*)d_in[7],  *bh0 = (const float*)d_in[8];
    const float* Wr1 = (const float*)d_in[9],  *Wz1 = (const float*)d_in[10], *Wh1 = (const float*)d_in[11];
    const float* br1 = (const float*)d_in[12], *bz1 = (const float*)d_in[13], *bh1 = (const float*)d_in[14];
    const float* Wfc = (const float*)d_in[15], *bfc = (const float*)d_in[16];
    const float* Wout = (const float*)d_in[17], *bout = (const float*)d_in[18];
    float* out = (float*)d_out;

    k_init<<<(BH + 255) / 256, 256>>>(h_init);
    k_embed<<<dim3(HH / 64, (SS * BB) / 64, 3), 256>>>(ids, emb, Wr0, Wz0, Wh0, br0, bz0, bh0);

    for (int t = 0; t < SS; ++t) {
        k_gates0<<<dim3(HH / 8, 2), 128>>>(t, Wr0, Wz0);
        k_cand0<<<HH / 8, 128>>>(t, Wh0);
        k_fc<<<HH / 8, 128>>>(Wfc, bfc);
        k_gates1<<<dim3(HH / 8, 2), 128>>>(Wr1, Wz1, br1, bz1);
        k_cand1<<<HH / 8, 128>>>(t, Wh1, bh1);
    }

    k_out<<<dim3((VV + 63) / 64, (SS * BB) / 64), 256>>>(Wout, bout, out);
    k_hfinal<<<(BH + 255) / 256, 256>>>(out + (size_t)SS * BB * VV);
}

// round 3
// speedup vs baseline: 1.2672x; 1.2672x over previous
#include <cuda_runtime.h>
#include <math.h>

#define VV 10000
#define EE 512
#define HH 1024
#define SS 64
#define BB 64

#define SBH (SS*BB*HH)
#define BH  (BB*HH)

// ---------------- device scratch (no cudaMalloc allowed) ----------------
__device__ float g_X0[3u * SBH];        // precomputed x-side of layer0 gates (+bias)
__device__ float g_H1all[SBH];          // all layer-1 hidden states (for batched Wout GEMM)
__device__ float g_h0[BH];              // layer0 hidden state
__device__ float g_rh0[BH];             // r0 * h0
__device__ float g_z0[BH];
__device__ float g_z1[BH];
__device__ float g_cat1[BB * 2 * HH];   // [x1, h1]
__device__ float g_cat1h[BB * 2 * HH];  // [x1, r1*h1]

__device__ __forceinline__ float sigm(float x) { return 1.0f / (1.0f + __expf(-x)); }

// ---------------- init ----------------
__global__ void k_init(const float* __restrict__ h_init) {
    int i = blockIdx.x * blockDim.x + threadIdx.x;
    if (i < BH) {
        g_h0[i] = h_init[i];
        int b = i >> 10, n = i & (HH - 1);
        g_cat1[b * 2 * HH + HH + n] = h_init[BH + i];
    }
}

// ---------------- big-tile GEMM for embedding precompute (64x64x16) ----------------
__global__ __launch_bounds__(256) void k_embed(
    const int* __restrict__ ids, const float* __restrict__ emb,
    const float* __restrict__ Wr, const float* __restrict__ Wz, const float* __restrict__ Wh,
    const float* __restrict__ br, const float* __restrict__ bz, const float* __restrict__ bh)
{
    const int g = blockIdx.z;
    const float* __restrict__ W    = (g == 0) ? Wr : ((g == 1) ? Wz : Wh);
    const float* __restrict__ bias = (g == 0) ? br : ((g == 1) ? bz : bh);
    float* __restrict__ out = g_X0 + (size_t)g * SBH;

    __shared__ __align__(16) float As[16][68];
    __shared__ __align__(16) float Ws[16][64];
    const int tid = threadIdx.x;
    const int bm = blockIdx.y * 64, bn = blockIdx.x * 64;
    const int lr = tid >> 2, lk = (tid & 3) * 4;
    const int wk = tid >> 4, wn = (tid & 15) * 4;
    const int tx = tid & 15, ty = tid >> 4;
    const float* __restrict__ arow = emb + (size_t)ids[bm + lr] * EE + lk;

    float acc[4][4];
#pragma unroll
    for (int i = 0; i < 4; i++)
#pragma unroll
        for (int j = 0; j < 4; j++) acc[i][j] = 0.f;

    for (int k0 = 0; k0 < EE; k0 += 16) {
        float4 av = *(const float4*)(arow + k0);
        As[lk + 0][lr] = av.x; As[lk + 1][lr] = av.y;
        As[lk + 2][lr] = av.z; As[lk + 3][lr] = av.w;
        *(float4*)&Ws[wk][wn] = *(const float4*)(W + (size_t)(k0 + wk) * HH + bn + wn);
        __syncthreads();
#pragma unroll
        for (int kk = 0; kk < 16; kk++) {
            float4 a = *(const float4*)&As[kk][ty * 4];
            float4 w = *(const float4*)&Ws[kk][tx * 4];
            acc[0][0] += a.x * w.x; acc[0][1] += a.x * w.y; acc[0][2] += a.x * w.z; acc[0][3] += a.x * w.w;
            acc[1][0] += a.y * w.x; acc[1][1] += a.y * w.y; acc[1][2] += a.y * w.z; acc[1][3] += a.y * w.w;
            acc[2][0] += a.z * w.x; acc[2][1] += a.z * w.y; acc[2][2] += a.z * w.z; acc[2][3] += a.z * w.w;
            acc[3][0] += a.w * w.x; acc[3][1] += a.w * w.y; acc[3][2] += a.w * w.z; acc[3][3] += a.w * w.w;
        }
        __syncthreads();
    }
    float4 bv = *(const float4*)(bias + bn + tx * 4);
#pragma unroll
    for (int i = 0; i < 4; i++) {
        int row = bm + ty * 4 + i;
        float* o = out + (size_t)row * HH + bn + tx * 4;
        o[0] = acc[i][0] + bv.x; o[1] = acc[i][1] + bv.y;
        o[2] = acc[i][2] + bv.z; o[3] = acc[i][3] + bv.w;
    }
}

// ---------------- k_out: logits = H1all @ Wout + bout  (M=4096, N=10000, K=1024) ----------------
__global__ __launch_bounds__(256) void k_out(
    const float* __restrict__ Wout, const float* __restrict__ bout,
    float* __restrict__ logits)
{
    __shared__ __align__(16) float As[16][68];
    __shared__ __align__(16) float Ws[16][64];
    const int tid = threadIdx.x;
    const int bm = blockIdx.y * 64, bn = blockIdx.x * 64;
    const int lr = tid >> 2, lk = (tid & 3) * 4;
    const int wk = tid >> 4, wn = (tid & 15) * 4;
    const int tx = tid & 15, ty = tid >> 4;
    const float* __restrict__ arow = g_H1all + (size_t)(bm + lr) * HH + lk;
    const bool wok = (bn + wn + 3) < VV;

    float acc[4][4];
#pragma unroll
    for (int i = 0; i < 4; i++)
#pragma unroll
        for (int j = 0; j < 4; j++) acc[i][j] = 0.f;

    for (int k0 = 0; k0 < HH; k0 += 16) {
        float4 av = *(const float4*)(arow + k0);
        As[lk + 0][lr] = av.x; As[lk + 1][lr] = av.y;
        As[lk + 2][lr] = av.z; As[lk + 3][lr] = av.w;
        float4 wv;
        const float* wp = Wout + (size_t)(k0 + wk) * VV;
        if (wok) {
            wv = *(const float4*)(wp + bn + wn);
        } else {
            wv.x = (bn + wn + 0 < VV) ? wp[bn + wn + 0] : 0.f;
            wv.y = (bn + wn + 1 < VV) ? wp[bn + wn + 1] : 0.f;
            wv.z = (bn + wn + 2 < VV) ? wp[bn + wn + 2] : 0.f;
            wv.w = (bn + wn + 3 < VV) ? wp[bn + wn + 3] : 0.f;
        }
        *(float4*)&Ws[wk][wn] = wv;
        __syncthreads();
#pragma unroll
        for (int kk = 0; kk < 16; kk++) {
            float4 a = *(const float4*)&As[kk][ty * 4];
            float4 w = *(const float4*)&Ws[kk][tx * 4];
            acc[0][0] += a.x * w.x; acc[0][1] += a.x * w.y; acc[0][2] += a.x * w.z; acc[0][3] += a.x * w.w;
            acc[1][0] += a.y * w.x; acc[1][1] += a.y * w.y; acc[1][2] += a.y * w.z; acc[1][3] += a.y * w.w;
            acc[2][0] += a.z * w.x; acc[2][1] += a.z * w.y; acc[2][2] += a.z * w.z; acc[2][3] += a.z * w.w;
            acc[3][0] += a.w * w.x; acc[3][1] += a.w * w.y; acc[3][2] += a.w * w.z; acc[3][3] += a.w * w.w;
        }
        __syncthreads();
    }
#pragma unroll
    for (int i = 0; i < 4; i++) {
        int row = bm + ty * 4 + i;
#pragma unroll
        for (int j = 0; j < 4; j++) {
            int col = bn + tx * 4 + j;
            if (col < VV) logits[(size_t)row * VV + col] = acc[i][j] + bout[col];
        }
    }
}

// ============ step GEMM v2: double-buffered, register-staged pipeline ============
// C[64, BN] tile of A[64,K] @ W[K, N(=HH stride)], 128 threads.
// BN=8  -> NPT=1 (4 outputs/thread), grid 128 CTAs over N=1024
// BN=16 -> NPT=2 (8 outputs/thread), grid 64 CTAs over N=1024
template<int BN>
__device__ __forceinline__ void step_gemm2(
    const float* __restrict__ A, int lda, int K,
    const float* __restrict__ W, int bn, float* __restrict__ acc)
{
    constexpr int NPT = BN / 8;   // n per thread
    constexpr int WPT = BN / 4;   // W floats loaded per thread per chunk
    __shared__ __align__(16) float As[2][32][68];
    __shared__ __align__(16) float Ws[2][32][BN];

    const int tid = threadIdx.x;
    const int ar = tid >> 1, ak = (tid & 1) * 16;       // A load: row, k-base
    const int wr = tid >> 2, wn = (tid & 3) * WPT;      // W load: row, n-base
    const int mg = tid >> 3;                            // compute: m-group (0..15)
    const int col = (tid & 7) * NPT;                    // compute: n offset

    const float* __restrict__ Arow = A + (size_t)ar * lda + ak;
    const float* __restrict__ Wbase = W + bn + wn + (size_t)wr * HH;

#pragma unroll
    for (int i = 0; i < 4 * NPT; i++) acc[i] = 0.f;

    float a_st[16];
    float w_st[WPT];

    // prologue: chunk 0 -> regs -> smem[0]
#pragma unroll
    for (int j = 0; j < 4; j++) {
        float4 v = *(const float4*)(Arow + j * 4);
        a_st[j * 4 + 0] = v.x; a_st[j * 4 + 1] = v.y;
        a_st[j * 4 + 2] = v.z; a_st[j * 4 + 3] = v.w;
    }
    if (WPT == 4) {
        float4 v = *(const float4*)(Wbase);
        w_st[0] = v.x; w_st[1] = v.y; w_st[2] = v.z; w_st[3] = v.w;
    } else {
        float2 v = *(const float2*)(Wbase);
        w_st[0] = v.x; w_st[1] = v.y;
    }
#pragma unroll
    for (int j = 0; j < 16; j++) As[0][ak + j][ar] = a_st[j];
#pragma unroll
    for (int j = 0; j < WPT; j++) Ws[0][wr][wn + j] = w_st[j];
    __syncthreads();

    const int C = K / 32;
    int buf = 0;
    for (int c = 0; c < C; ++c) {
        const bool more = (c + 1 < C);
        if (more) {
            const int k0 = (c + 1) * 32;
#pragma unroll
            for (int j = 0; j < 4; j++) {
                float4 v = *(const float4*)(Arow + k0 + j * 4);
                a_st[j * 4 + 0] = v.x; a_st[j * 4 + 1] = v.y;
                a_st[j * 4 + 2] = v.z; a_st[j * 4 + 3] = v.w;
            }
            const float* wp = Wbase + (size_t)k0 * HH;
            if (WPT == 4) {
                float4 v = *(const float4*)(wp);
                w_st[0] = v.x; w_st[1] = v.y; w_st[2] = v.z; w_st[3] = v.w;
            } else {
                float2 v = *(const float2*)(wp);
                w_st[0] = v.x; w_st[1] = v.y;
            }
        }
        // compute current chunk (overlaps with LDGs above in flight)
#pragma unroll
        for (int kk = 0; kk < 32; ++kk) {
            float4 a = *(const float4*)&As[buf][kk][mg * 4];
            if (NPT == 2) {
                float2 w = *(const float2*)&Ws[buf][kk][col];
                acc[0] += a.x * w.x; acc[1] += a.x * w.y;
                acc[2] += a.y * w.x; acc[3] += a.y * w.y;
                acc[4] += a.z * w.x; acc[5] += a.z * w.y;
                acc[6] += a.w * w.x; acc[7] += a.w * w.y;
            } else {
                float w = Ws[buf][kk][col];
                acc[0] += a.x * w; acc[1] += a.y * w;
                acc[2] += a.z * w; acc[3] += a.w * w;
            }
        }
        if (more) {
#pragma unroll
            for (int j = 0; j < 16; j++) As[buf ^ 1][ak + j][ar] = a_st[j];
#pragma unroll
            for (int j = 0; j < WPT; j++) Ws[buf ^ 1][wr][wn + j] = w_st[j];
            __syncthreads();
            buf ^= 1;
        }
    }
}

// r0/z0: sigma(X0[g][t] + h0 @ W{r,z}0[E:,:]);  r-branch stores r*h0
__global__ __launch_bounds__(128) void k_gates0(int t,
    const float* __restrict__ Wr0, const float* __restrict__ Wz0)
{
    const int bn = blockIdx.x * 16;
    const int gate = blockIdx.y;
    const float* W = (gate ? Wz0 : Wr0) + (size_t)EE * HH;
    float acc[8];
    step_gemm2<16>(g_h0, HH, HH, W, bn, acc);
    const float* X = g_X0 + (size_t)gate * SBH + (size_t)t * BH;
    const int mg = threadIdx.x >> 3, col = (threadIdx.x & 7) * 2;
#pragma unroll
    for (int i = 0; i < 4; i++)
#pragma unroll
        for (int j = 0; j < 2; j++) {
            int idx = (mg * 4 + i) * HH + bn + col + j;
            float v = sigm(acc[i * 2 + j] + X[idx]);
            if (gate == 0) g_rh0[idx] = v * g_h0[idx];
            else           g_z0[idx] = v;
        }
}

// hh0 = sigma(X0[2][t] + (r*h0) @ Wh0[E:,:]);  h0 <- (1-z)*h0 + z*hh0
__global__ __launch_bounds__(128) void k_cand0(int t, const float* __restrict__ Wh0)
{
    const int bn = blockIdx.x * 8;
    float acc[4];
    step_gemm2<8>(g_rh0, HH, HH, Wh0 + (size_t)EE * HH, bn, acc);
    const float* X = g_X0 + 2ull * SBH + (size_t)t * BH;
    const int mg = threadIdx.x >> 3, col = threadIdx.x & 7;
#pragma unroll
    for (int i = 0; i < 4; i++) {
        int idx = (mg * 4 + i) * HH + bn + col;
        float hh = sigm(acc[i] + X[idx]);
        float h = g_h0[idx], z = g_z0[idx];
        g_h0[idx] = (1.f - z) * h + z * hh;
    }
}

// x1 = sigma(h0 @ Wfc + bfc) -> cat1[:, :H], cat1h[:, :H]
__global__ __launch_bounds__(128) void k_fc(
    const float* __restrict__ Wfc, const float* __restrict__ bfc)
{
    const int bn = blockIdx.x * 8;
    float acc[4];
    step_gemm2<8>(g_h0, HH, HH, Wfc, bn, acc);
    const int mg = threadIdx.x >> 3, col = threadIdx.x & 7;
#pragma unroll
    for (int i = 0; i < 4; i++) {
        int b = mg * 4 + i, n = bn + col;
        float x1 = sigm(acc[i] + bfc[n]);
        g_cat1[b * 2 * HH + n] = x1;
        g_cat1h[b * 2 * HH + n] = x1;
    }
}

// r1/z1 = sigma([x1,h1] @ W{r,z}1 + b);  r-branch stores r1*h1 into cat1h[:, H:]
__global__ __launch_bounds__(128) void k_gates1(
    const float* __restrict__ Wr1, const float* __restrict__ Wz1,
    const float* __restrict__ br1, const float* __restrict__ bz1)
{
    const int bn = blockIdx.x * 16;
    const int gate = blockIdx.y;
    const float* W = gate ? Wz1 : Wr1;
    const float* bias = gate ? bz1 : br1;
    float acc[8];
    step_gemm2<16>(g_cat1, 2 * HH, 2 * HH, W, bn, acc);
    const int mg = threadIdx.x >> 3, col = (threadIdx.x & 7) * 2;
#pragma unroll
    for (int i = 0; i < 4; i++)
#pragma unroll
        for (int j = 0; j < 2; j++) {
            int b = mg * 4 + i, n = bn + col + j;
            float v = sigm(acc[i * 2 + j] + bias[n]);
            if (gate == 0) {
                float h1 = g_cat1[b * 2 * HH + HH + n];
                g_cat1h[b * 2 * HH + HH + n] = v * h1;
            } else {
                g_z1[b * HH + n] = v;
            }
        }
}

// hh1 = sigma([x1, r1*h1] @ Wh1 + bh1); h1 <- (1-z1)*h1 + z1*hh1; store into H1all[t]
__global__ __launch_bounds__(128) void k_cand1(int t,
    const float* __restrict__ Wh1, const float* __restrict__ bh1)
{
    const int bn = blockIdx.x * 8;
    float acc[4];
    step_gemm2<8>(g_cat1h, 2 * HH, 2 * HH, Wh1, bn, acc);
    const int mg = threadIdx.x >> 3, col = threadIdx.x & 7;
#pragma unroll
    for (int i = 0; i < 4; i++) {
        int b = mg * 4 + i, n = bn + col;
        float hh = sigm(acc[i] + bh1[n]);
        float h1 = g_cat1[b * 2 * HH + HH + n];
        float z  = g_z1[b * HH + n];
        float hn = (1.f - z) * h1 + z * hh;
        g_cat1[b * 2 * HH + HH + n] = hn;
        g_H1all[(size_t)t * BH + b * HH + n] = hn;
    }
}

// h_final = [h0, h1] appended after logits
__global__ void k_hfinal(float* __restrict__ out) {
    int i = blockIdx.x * blockDim.x + threadIdx.x;
    if (i < BH) {
        out[i] = g_h0[i];
        int b = i >> 10, n = i & (HH - 1);
        out[BH + i] = g_cat1[b * 2 * HH + HH + n];
    }
}

extern "C" void kernel_launch(void* const* d_in, const int* in_sizes, int n_in,
                              void* d_out, int out_size)
{
    const int*   ids    = (const int*)d_in[0];
    const float* h_init = (const float*)d_in[1];
    const float* emb    = (const float*)d_in[2];
    const float* Wr0 = (const float*)d_in[3],  *Wz0 = (const float*)d_in[4],  *Wh0 = (const float*)d_in[5];
    const float* br0 = (const float*)d_in[6],  *bz0 = (const float*)d_in[7],  *bh0 = (const float*)d_in[8];
    const float* Wr1 = (const float*)d_in[9],  *Wz1 = (const float*)d_in[10], *Wh1 = (const float*)d_in[11];
    const float* br1 = (const float*)d_in[12], *bz1 = (const float*)d_in[13], *bh1 = (const float*)d_in[14];
    const float* Wfc = (const float*)d_in[15], *bfc = (const float*)d_in[16];
    const float* Wout = (const float*)d_in[17], *bout = (const float*)d_in[18];
    float* out = (float*)d_out;

    k_init<<<(BH + 255) / 256, 256>>>(h_init);
    k_embed<<<dim3(HH / 64, (SS * BB) / 64, 3), 256>>>(ids, emb, Wr0, Wz0, Wh0, br0, bz0, bh0);

    for (int t = 0; t < SS; ++t) {
        k_gates0<<<dim3(HH / 16, 2), 128>>>(t, Wr0, Wz0);
        k_cand0<<<HH / 8, 128>>>(t, Wh0);
        k_fc<<<HH / 8, 128>>>(Wfc, bfc);
        k_gates1<<<dim3(HH / 16, 2), 128>>>(Wr1, Wz1, br1, bz1);
        k_cand1<<<HH / 8, 128>>>(t, Wh1, bh1);
    }

    k_out<<<dim3((VV + 63) / 64, (SS * BB) / 64), 256>>>(Wout, bout, out);
    k_hfinal<<<(BH + 255) / 256, 256>>>(out + (size_t)SS * BB * VV);
}